// round 16
// baseline (speedup 1.0000x reference)
#include <cuda_runtime.h>
#include <cstdint>

// PatchEmbedding: x(1,3,384,384) f32, W(768,12), b(768), positions(768,146689)
// out[e,l] = b[e] + positions[e,l] + sum_d patch[d,l] * W[e,d]
//
// W/b in __constant__ (uniform const port). pos streamed into smem by a
// single-thread cp.async.bulk + mbarrier ring. Each thread computes the
// ADJACENT pair (l, l+1) in scalar math: W/b uniform loads amortized 2x,
// pos read as LDS.64 and result stored as STG.64 on even e-rows.
// launch_bounds(256,5): 40 warps/SM (regs 48 fits the 51-reg cap).

#define IMG      384
#define LW       383
#define L_TOTAL  146689              // 383*383
#define EMB      768
#define PD       12

#define TPB      256
#define L_TILE   512                 // 2 adjacent l per thread
#define E_TILE   32                  // 768/32 = 24 y-blocks (6888 blocks total)
#define CH       4                   // e-rows per stage
#define NCH      (E_TILE / CH)       // 8 stages of work
#define NSTAGE   4                   // ring depth (each slot reused twice)

// Stage row: 520 floats (2080B, 16B-multiple). Copy starts at src - (e&3)
// floats so the bulk source is 16B-aligned; since e0 % 32 == 0 and stages
// advance by CH=4, (e&3) == j for row j of any stage.
#define ROWF     520
#define ROWB     (ROWF * 4)          // 2080
#define STAGEF   (CH * ROWF)         // 2080 floats
#define STAGEB   (CH * ROWB)         // 8320 bytes

__constant__ float4 cW4[EMB * 3];
__constant__ float  cB[EMB];

__device__ __forceinline__ void gather_patch(const float* __restrict__ x,
                                             int l, float* p) {
    const int r   = l / LW;
    const int col = l - r * LW;
    const float* xp = x + r * IMG + col;
    #pragma unroll
    for (int c = 0; c < 3; c++)
        #pragma unroll
        for (int i = 0; i < 2; i++)
            #pragma unroll
            for (int j = 0; j < 2; j++)
                p[c * 4 + i * 2 + j] = xp[c * IMG * IMG + i * IMG + j];
}

// bias folded into chain head.
__device__ __forceinline__ float dot12b(const float* p, float bb,
                                        float4 w0, float4 w1, float4 w2) {
    float c0 = fmaf(p[0], w0.x, bb);
    float c1 = p[1] * w0.y;
    c0 = fmaf(p[2],  w0.z, c0);  c1 = fmaf(p[3],  w0.w, c1);
    c0 = fmaf(p[4],  w1.x, c0);  c1 = fmaf(p[5],  w1.y, c1);
    c0 = fmaf(p[6],  w1.z, c0);  c1 = fmaf(p[7],  w1.w, c1);
    c0 = fmaf(p[8],  w2.x, c0);  c1 = fmaf(p[9],  w2.y, c1);
    c0 = fmaf(p[10], w2.z, c0);  c1 = fmaf(p[11], w2.w, c1);
    return c0 + c1;
}

__device__ __forceinline__ void mbar_init(uint32_t bar, uint32_t cnt) {
    asm volatile("mbarrier.init.shared.b64 [%0], %1;" :: "r"(bar), "r"(cnt) : "memory");
}
__device__ __forceinline__ void mbar_expect_tx(uint32_t bar, uint32_t bytes) {
    asm volatile("mbarrier.arrive.expect_tx.shared.b64 _, [%0], %1;"
                 :: "r"(bar), "r"(bytes) : "memory");
}
__device__ __forceinline__ void mbar_arrive(uint32_t bar) {
    asm volatile("mbarrier.arrive.shared.b64 _, [%0];" :: "r"(bar) : "memory");
}
__device__ __forceinline__ void mbar_wait(uint32_t bar, uint32_t parity) {
    asm volatile(
        "{\n\t.reg .pred P;\n\t"
        "W%=:\n\t"
        "mbarrier.try_wait.parity.shared.b64 P, [%0], %1, 0x989680;\n\t"
        "@P bra.uni D%=;\n\t"
        "bra.uni W%=;\n\t"
        "D%=:\n\t}"
        :: "r"(bar), "r"(parity) : "memory");
}
__device__ __forceinline__ void bulk_cp(uint32_t dst, const float* src,
                                        uint32_t bar) {
    asm volatile(
        "cp.async.bulk.shared::cta.global.mbarrier::complete_tx::bytes "
        "[%0], [%1], %2, [%3];"
        :: "r"(dst), "l"(src), "r"((uint32_t)ROWB), "r"(bar) : "memory");
}

__global__ __launch_bounds__(TPB, 5)
void patch_embed_kernel(const float* __restrict__ x,
                        const float* __restrict__ pos,
                        float* __restrict__ out) {
    __shared__ __align__(16) float spv[NSTAGE * STAGEF];   // 33,280 B
    __shared__ __align__(8)  unsigned long long mbar[2 * NSTAGE];

    const int e0 = blockIdx.y * E_TILE;
    const int l0 = blockIdx.x * L_TILE;
    const int la = l0 + 2 * threadIdx.x;

    if (blockIdx.x == gridDim.x - 1) {
        // ---- tail x-block: 257 valid l; scalar bounds-checked path ----
        #pragma unroll 1
        for (int k = 0; k < 2; k++) {
            const int l = la + k;
            if (l >= L_TOTAL) continue;
            float p[PD];
            gather_patch(x, l, p);
            for (int ee = 0; ee < E_TILE; ee++) {
                const int e = e0 + ee;
                const float4 w0 = cW4[e * 3 + 0];
                const float4 w1 = cW4[e * 3 + 1];
                const float4 w2 = cW4[e * 3 + 2];
                const float pvv = pos[(size_t)e * L_TOTAL + l];
                out[(size_t)e * L_TOTAL + l] =
                    dot12b(p, cB[e], w0, w1, w2) + pvv;
            }
        }
        return;
    }

    // ---- full blocks ----
    const uint32_t sbase = (uint32_t)__cvta_generic_to_shared(spv);
    const uint32_t bbase = (uint32_t)__cvta_generic_to_shared(mbar);
    #define FULLB(s)  (bbase + (uint32_t)(s) * 8u)
    #define EMPTYB(s) (bbase + (uint32_t)(NSTAGE + (s)) * 8u)

    if (threadIdx.x == 0) {
        #pragma unroll
        for (int s = 0; s < NSTAGE; s++) {
            mbar_init(FULLB(s), 1);
            mbar_init(EMPTYB(s), TPB);
        }
        asm volatile("fence.proxy.async.shared::cta;" ::: "memory");
    }

    // Adjacent patch pair; gathers share cache lines, all L2/L1-hot.
    float p[2][PD];
    gather_patch(x, la,     p[0]);
    gather_patch(x, la + 1, p[1]);

    __syncthreads();   // mbarriers visible before any use

    const float* __restrict__ posblk = pos + (size_t)e0 * L_TOTAL + l0;
    float*       __restrict__ outbase = out + (size_t)e0 * L_TOTAL + la;

    // Prologue: issue stages 0..NSTAGE-2.
    if (threadIdx.x == 0) {
        #pragma unroll
        for (int s = 0; s < NSTAGE - 1; s++) {
            mbar_expect_tx(FULLB(s), STAGEB);
            #pragma unroll
            for (int j = 0; j < CH; j++)
                bulk_cp(sbase + (uint32_t)(s * STAGEB + j * ROWB),
                        posblk + (size_t)(s * CH + j) * L_TOTAL - j,
                        FULLB(s));
        }
    }

    #pragma unroll
    for (int cc = 0; cc < NCH; cc++) {
        // Inline producer: issue stage cc+NSTAGE-1 before consuming cc.
        if (threadIdx.x == 0) {
            const int s = cc + NSTAGE - 1;
            if (s < NCH) {
                const int st = s % NSTAGE;
                const int k  = s / NSTAGE;
                if (k > 0)
                    mbar_wait(EMPTYB(st), (uint32_t)((k - 1) & 1));
                mbar_expect_tx(FULLB(st), STAGEB);
                #pragma unroll
                for (int j = 0; j < CH; j++)
                    bulk_cp(sbase + (uint32_t)(st * STAGEB + j * ROWB),
                            posblk + (size_t)(s * CH + j) * L_TOTAL - j,
                            FULLB(st));
            }
        }

        const int st = cc % NSTAGE;
        mbar_wait(FULLB(st), (uint32_t)((cc / NSTAGE) & 1));

        #pragma unroll
        for (int j = 0; j < CH; j++) {
            const int e = e0 + cc * CH + j;
            const float4 w0 = cW4[e * 3 + 0];   // uniform const port, shared by pair
            const float4 w1 = cW4[e * 3 + 1];
            const float4 w2 = cW4[e * 3 + 2];
            const float  bb = cB[e];

            // smem offset parity == j parity (ROWF, STAGEF even; shift == j).
            const int off = st * STAGEF + j * ROWF + j + 2 * threadIdx.x;
            float pv0, pv1;
            if ((j & 1) == 0) {
                const float2 pv = *(const float2*)&spv[off];
                pv0 = pv.x; pv1 = pv.y;
            } else {
                pv0 = spv[off]; pv1 = spv[off + 1];
            }

            const float o0 = dot12b(p[0], bb, w0, w1, w2) + pv0;
            const float o1 = dot12b(p[1], bb, w0, w1, w2) + pv1;

            // gmem addr parity == e parity == j parity (L odd, la even).
            float* op = outbase + (size_t)(cc * CH + j) * L_TOTAL;
            if ((j & 1) == 0) {
                __stcs((float2*)op, make_float2(o0, o1));
            } else {
                __stcs(op,     o0);
                __stcs(op + 1, o1);
            }
        }

        mbar_arrive(EMPTYB(st));
    }
}

extern "C" void kernel_launch(void* const* d_in, const int* in_sizes, int n_in,
                              void* d_out, int out_size) {
    const float* x   = (const float*)d_in[0];
    const float* W   = (const float*)d_in[1];
    const float* b   = (const float*)d_in[2];
    const float* pos = (const float*)d_in[3];
    float* out = (float*)d_out;

    cudaMemcpyToSymbolAsync(cW4, W, EMB * PD * sizeof(float), 0,
                            cudaMemcpyDeviceToDevice);
    cudaMemcpyToSymbolAsync(cB, b, EMB * sizeof(float), 0,
                            cudaMemcpyDeviceToDevice);

    dim3 grid((L_TOTAL + L_TILE - 1) / L_TILE,   // 287 (last = tail path)
              EMB / E_TILE,                      // 24
              1);
    patch_embed_kernel<<<grid, TPB>>>(x, pos, out);
}

// round 17
// speedup vs baseline: 1.0108x; 1.0108x over previous
#include <cuda_runtime.h>
#include <cstdint>

// PatchEmbedding: x(1,3,384,384) f32, W(768,12), b(768), positions(768,146689)
// out[e,l] = b[e] + positions[e,l] + sum_d patch[d,l] * W[e,d]
//
// W/b in __constant__ (uniform const port; rematerializable under register
// pressure -> no spills at tight bounds). pos streamed into smem by a
// single-thread cp.async.bulk + mbarrier ring (3-deep). Each thread computes
// the ADJACENT pair (l, l+1): W/b loads amortized 2x, LDS.64 / STG.64 on
// even e-rows. launch_bounds(256,6): 48 warps/SM.

#define IMG      384
#define LW       383
#define L_TOTAL  146689              // 383*383
#define EMB      768
#define PD       12

#define TPB      256
#define L_TILE   512                 // 2 adjacent l per thread
#define E_TILE   32                  // 768/32 = 24 y-blocks (6888 blocks total)
#define CH       4                   // e-rows per stage
#define NCH      (E_TILE / CH)       // 8 stages of work
#define NSTAGE   3                   // ring depth (R9-validated parity schedule)

// Stage row: 520 floats (2080B, 16B-multiple). Copy starts at src - (e&3)
// floats so the bulk source is 16B-aligned; since e0 % 32 == 0 and stages
// advance by CH=4, (e&3) == j for row j of any stage.
#define ROWF     520
#define ROWB     (ROWF * 4)          // 2080
#define STAGEF   (CH * ROWF)         // 2080 floats
#define STAGEB   (CH * ROWB)         // 8320 bytes

__constant__ float4 cW4[EMB * 3];
__constant__ float  cB[EMB];

__device__ __forceinline__ void gather_patch(const float* __restrict__ x,
                                             int l, float* p) {
    const int r   = l / LW;
    const int col = l - r * LW;
    const float* xp = x + r * IMG + col;
    #pragma unroll
    for (int c = 0; c < 3; c++)
        #pragma unroll
        for (int i = 0; i < 2; i++)
            #pragma unroll
            for (int j = 0; j < 2; j++)
                p[c * 4 + i * 2 + j] = xp[c * IMG * IMG + i * IMG + j];
}

// bias folded into chain head.
__device__ __forceinline__ float dot12b(const float* p, float bb,
                                        float4 w0, float4 w1, float4 w2) {
    float c0 = fmaf(p[0], w0.x, bb);
    float c1 = p[1] * w0.y;
    c0 = fmaf(p[2],  w0.z, c0);  c1 = fmaf(p[3],  w0.w, c1);
    c0 = fmaf(p[4],  w1.x, c0);  c1 = fmaf(p[5],  w1.y, c1);
    c0 = fmaf(p[6],  w1.z, c0);  c1 = fmaf(p[7],  w1.w, c1);
    c0 = fmaf(p[8],  w2.x, c0);  c1 = fmaf(p[9],  w2.y, c1);
    c0 = fmaf(p[10], w2.z, c0);  c1 = fmaf(p[11], w2.w, c1);
    return c0 + c1;
}

__device__ __forceinline__ void mbar_init(uint32_t bar, uint32_t cnt) {
    asm volatile("mbarrier.init.shared.b64 [%0], %1;" :: "r"(bar), "r"(cnt) : "memory");
}
__device__ __forceinline__ void mbar_expect_tx(uint32_t bar, uint32_t bytes) {
    asm volatile("mbarrier.arrive.expect_tx.shared.b64 _, [%0], %1;"
                 :: "r"(bar), "r"(bytes) : "memory");
}
__device__ __forceinline__ void mbar_arrive(uint32_t bar) {
    asm volatile("mbarrier.arrive.shared.b64 _, [%0];" :: "r"(bar) : "memory");
}
__device__ __forceinline__ void mbar_wait(uint32_t bar, uint32_t parity) {
    asm volatile(
        "{\n\t.reg .pred P;\n\t"
        "W%=:\n\t"
        "mbarrier.try_wait.parity.shared.b64 P, [%0], %1, 0x989680;\n\t"
        "@P bra.uni D%=;\n\t"
        "bra.uni W%=;\n\t"
        "D%=:\n\t}"
        :: "r"(bar), "r"(parity) : "memory");
}
__device__ __forceinline__ void bulk_cp(uint32_t dst, const float* src,
                                        uint32_t bar) {
    asm volatile(
        "cp.async.bulk.shared::cta.global.mbarrier::complete_tx::bytes "
        "[%0], [%1], %2, [%3];"
        :: "r"(dst), "l"(src), "r"((uint32_t)ROWB), "r"(bar) : "memory");
}

__global__ __launch_bounds__(TPB, 6)   // reg cap 42; const operands remat, no spill
void patch_embed_kernel(const float* __restrict__ x,
                        const float* __restrict__ pos,
                        float* __restrict__ out) {
    __shared__ __align__(16) float spv[NSTAGE * STAGEF];   // 24,960 B
    __shared__ __align__(8)  unsigned long long mbar[2 * NSTAGE];

    const int e0 = blockIdx.y * E_TILE;
    const int l0 = blockIdx.x * L_TILE;
    const int la = l0 + 2 * threadIdx.x;

    if (blockIdx.x == gridDim.x - 1) {
        // ---- tail x-block: 257 valid l; scalar bounds-checked path ----
        #pragma unroll 1
        for (int k = 0; k < 2; k++) {
            const int l = la + k;
            if (l >= L_TOTAL) continue;
            float p[PD];
            gather_patch(x, l, p);
            for (int ee = 0; ee < E_TILE; ee++) {
                const int e = e0 + ee;
                const float4 w0 = cW4[e * 3 + 0];
                const float4 w1 = cW4[e * 3 + 1];
                const float4 w2 = cW4[e * 3 + 2];
                const float pvv = pos[(size_t)e * L_TOTAL + l];
                out[(size_t)e * L_TOTAL + l] =
                    dot12b(p, cB[e], w0, w1, w2) + pvv;
            }
        }
        return;
    }

    // ---- full blocks ----
    const uint32_t sbase = (uint32_t)__cvta_generic_to_shared(spv);
    const uint32_t bbase = (uint32_t)__cvta_generic_to_shared(mbar);
    #define FULLB(s)  (bbase + (uint32_t)(s) * 8u)
    #define EMPTYB(s) (bbase + (uint32_t)(NSTAGE + (s)) * 8u)

    if (threadIdx.x == 0) {
        #pragma unroll
        for (int s = 0; s < NSTAGE; s++) {
            mbar_init(FULLB(s), 1);
            mbar_init(EMPTYB(s), TPB);
        }
        asm volatile("fence.proxy.async.shared::cta;" ::: "memory");
    }

    // Adjacent patch pair; gathers share cache lines, all L2/L1-hot.
    float p[2][PD];
    gather_patch(x, la,     p[0]);
    gather_patch(x, la + 1, p[1]);

    __syncthreads();   // mbarriers visible before any use

    const float* __restrict__ posblk = pos + (size_t)e0 * L_TOTAL + l0;
    float*       __restrict__ outbase = out + (size_t)e0 * L_TOTAL + la;

    // Prologue: issue stages 0..NSTAGE-2.
    if (threadIdx.x == 0) {
        #pragma unroll
        for (int s = 0; s < NSTAGE - 1; s++) {
            mbar_expect_tx(FULLB(s), STAGEB);
            #pragma unroll
            for (int j = 0; j < CH; j++)
                bulk_cp(sbase + (uint32_t)(s * STAGEB + j * ROWB),
                        posblk + (size_t)(s * CH + j) * L_TOTAL - j,
                        FULLB(s));
        }
    }

    #pragma unroll
    for (int cc = 0; cc < NCH; cc++) {
        // Inline producer: issue stage cc+NSTAGE-1 before consuming cc.
        if (threadIdx.x == 0) {
            const int s = cc + NSTAGE - 1;
            if (s < NCH) {
                const int st = s % NSTAGE;
                const int k  = s / NSTAGE;
                if (k > 0)
                    mbar_wait(EMPTYB(st), (uint32_t)((k - 1) & 1));
                mbar_expect_tx(FULLB(st), STAGEB);
                #pragma unroll
                for (int j = 0; j < CH; j++)
                    bulk_cp(sbase + (uint32_t)(st * STAGEB + j * ROWB),
                            posblk + (size_t)(s * CH + j) * L_TOTAL - j,
                            FULLB(st));
            }
        }

        const int st = cc % NSTAGE;
        mbar_wait(FULLB(st), (uint32_t)((cc / NSTAGE) & 1));

        #pragma unroll
        for (int j = 0; j < CH; j++) {
            const int e = e0 + cc * CH + j;
            const float4 w0 = cW4[e * 3 + 0];   // uniform const port, shared by pair
            const float4 w1 = cW4[e * 3 + 1];
            const float4 w2 = cW4[e * 3 + 2];
            const float  bb = cB[e];

            // smem offset parity == j parity (ROWF, STAGEF even; shift == j).
            const int off = st * STAGEF + j * ROWF + j + 2 * threadIdx.x;
            float pv0, pv1;
            if ((j & 1) == 0) {
                const float2 pv = *(const float2*)&spv[off];
                pv0 = pv.x; pv1 = pv.y;
            } else {
                pv0 = spv[off]; pv1 = spv[off + 1];
            }

            const float o0 = dot12b(p[0], bb, w0, w1, w2) + pv0;
            const float o1 = dot12b(p[1], bb, w0, w1, w2) + pv1;

            // gmem addr parity == e parity == j parity (L odd, la even).
            float* op = outbase + (size_t)(cc * CH + j) * L_TOTAL;
            if ((j & 1) == 0) {
                __stcs((float2*)op, make_float2(o0, o1));
            } else {
                __stcs(op,     o0);
                __stcs(op + 1, o1);
            }
        }

        mbar_arrive(EMPTYB(st));
    }
}

extern "C" void kernel_launch(void* const* d_in, const int* in_sizes, int n_in,
                              void* d_out, int out_size) {
    const float* x   = (const float*)d_in[0];
    const float* W   = (const float*)d_in[1];
    const float* b   = (const float*)d_in[2];
    const float* pos = (const float*)d_in[3];
    float* out = (float*)d_out;

    cudaMemcpyToSymbolAsync(cW4, W, EMB * PD * sizeof(float), 0,
                            cudaMemcpyDeviceToDevice);
    cudaMemcpyToSymbolAsync(cB, b, EMB * sizeof(float), 0,
                            cudaMemcpyDeviceToDevice);

    dim3 grid((L_TOTAL + L_TILE - 1) / L_TILE,   // 287 (last = tail path)
              EMB / E_TILE,                      // 24
              1);
    patch_embed_kernel<<<grid, TPB>>>(x, pos, out);
}